// round 3
// baseline (speedup 1.0000x reference)
#include <cuda_runtime.h>

#define SZ_OUT (64ull * 1024ull * 64ull)
#define STRIP 1025

// ---------------------------------------------------------------------------
// Kernel 1: bias[b,q,k] = sum_d Q[b,q,d] * R_k[q,k,d]   (written into attn
// region as scratch; only causal tiles). Grid: (16 k-tiles, 1024 q).
// ---------------------------------------------------------------------------
__global__ void __launch_bounds__(256) k_bias(const float* __restrict__ Q,
                                              const float* __restrict__ Rk,
                                              float* __restrict__ attn)
{
    const int q  = blockIdx.y;
    const int k0 = blockIdx.x << 6;
    if (k0 > q) return;

    __shared__ float sQd[64 * 68];   // [d][b]
    __shared__ float sRt[64 * 68];   // [d][kk]
    const int tid = threadIdx.x;

    #pragma unroll
    for (int i = 0; i < 16; i++) {
        int f = tid + (i << 8); int b = f >> 6, d = f & 63;
        sQd[d * 68 + b] = Q[((size_t)b << 16) + ((size_t)q << 6) + d];
    }
    #pragma unroll
    for (int i = 0; i < 16; i++) {
        int f = tid + (i << 8); int kk = f >> 6, d = f & 63;
        sRt[d * 68 + kk] = Rk[(((size_t)q << 10) + (size_t)(k0 + kk)) * 64 + d];
    }
    __syncthreads();

    const int b0 = (tid >> 4) << 2, kk0 = (tid & 15) << 2;
    float acc[4][4] = {};
    #pragma unroll 8
    for (int d = 0; d < 64; d++) {
        float4 qv = *(const float4*)&sQd[d * 68 + b0];
        float4 rv = *(const float4*)&sRt[d * 68 + kk0];
        float qa[4] = {qv.x, qv.y, qv.z, qv.w};
        float ra[4] = {rv.x, rv.y, rv.z, rv.w};
        #pragma unroll
        for (int i = 0; i < 4; i++)
            #pragma unroll
            for (int j = 0; j < 4; j++)
                acc[i][j] = fmaf(qa[i], ra[j], acc[i][j]);
    }
    #pragma unroll
    for (int i = 0; i < 4; i++) {
        size_t base = ((size_t)(b0 + i) << 20) + ((size_t)q << 10) + (size_t)(k0 + kk0);
        *(float4*)&attn[base] = make_float4(acc[i][0], acc[i][1], acc[i][2], acc[i][3]);
    }
}

// ---------------------------------------------------------------------------
// Kernel 2: per (b, 32-row q strip): scores = (q@k^T + bias)*0.125, causal
// mask, softmax over full row in SMEM, write attn (zeros above diag), then
// fused attn@v -> out.  Grid: (64 b, 32 strips), 157 KB dynamic SMEM.
// ---------------------------------------------------------------------------
__global__ void __launch_bounds__(256) k_attn(const float* __restrict__ Q,
                                              const float* __restrict__ K,
                                              const float* __restrict__ V,
                                              float* attn,
                                              float* __restrict__ out)
{
    extern __shared__ float sm[];
    float* strip = sm;                       // [32][1025]
    float* sQt   = strip + 32 * STRIP;       // [qi][d]  stride 68
    float* sKV   = sQt + 32 * 68;            // [..][..] stride 68
    __shared__ float sInv[32];

    const int b   = blockIdx.x;
    const int q0  = blockIdx.y << 5;
    const int tid = threadIdx.x;
    const int ntile = ((q0 + 31) >> 6) + 1;

    #pragma unroll
    for (int i = 0; i < 8; i++) {
        int f = tid + (i << 8); int qi = f >> 6, d = f & 63;
        sQt[qi * 68 + d] = Q[((size_t)b << 16) + ((size_t)(q0 + qi) << 6) + d];
    }

    const int qi    = tid >> 3;
    const int kk0   = (tid & 7) << 3;
    const int q_row = q0 + qi;

    // ---- phase 1: scores strip ----
    for (int kt = 0; kt < ntile; kt++) {
        const int k0 = kt << 6;
        __syncthreads();
        #pragma unroll
        for (int i = 0; i < 16; i++) {
            int f = tid + (i << 8); int kk = f >> 6, d = f & 63;
            sKV[d * 68 + kk] = K[((size_t)b << 16) + ((size_t)(k0 + kk) << 6) + d];
        }
        __syncthreads();

        float acc[8] = {};
        #pragma unroll 8
        for (int d = 0; d < 64; d++) {
            float qv = sQt[qi * 68 + d];
            float4 a = *(const float4*)&sKV[d * 68 + kk0];
            float4 c = *(const float4*)&sKV[d * 68 + kk0 + 4];
            acc[0] = fmaf(qv, a.x, acc[0]); acc[1] = fmaf(qv, a.y, acc[1]);
            acc[2] = fmaf(qv, a.z, acc[2]); acc[3] = fmaf(qv, a.w, acc[3]);
            acc[4] = fmaf(qv, c.x, acc[4]); acc[5] = fmaf(qv, c.y, acc[5]);
            acc[6] = fmaf(qv, c.z, acc[6]); acc[7] = fmaf(qv, c.w, acc[7]);
        }
        #pragma unroll
        for (int j = 0; j < 8; j++) {
            int k = k0 + kk0 + j;
            float s = 0.f;
            if (k <= q_row)
                s = (acc[j] + attn[((size_t)b << 20) + ((size_t)q_row << 10) + k]) * 0.125f;
            strip[qi * STRIP + k] = s;
        }
    }
    __syncthreads();

    // ---- phase 2: softmax per row ----
    {
        const int lane = tid & 31, w = tid >> 5;
        for (int r = 0; r < 4; r++) {
            int row = (w << 2) + r;
            int qr  = q0 + row;
            float m = -1e30f;
            for (int kk = lane; kk <= qr; kk += 32)
                m = fmaxf(m, strip[row * STRIP + kk]);
            #pragma unroll
            for (int o = 16; o; o >>= 1)
                m = fmaxf(m, __shfl_xor_sync(0xffffffffu, m, o));
            float ssum = 0.f;
            for (int kk = lane; kk <= qr; kk += 32) {
                float e = __expf(strip[row * STRIP + kk] - m);
                strip[row * STRIP + kk] = e;
                ssum += e;
            }
            #pragma unroll
            for (int o = 16; o; o >>= 1)
                ssum += __shfl_xor_sync(0xffffffffu, ssum, o);
            if (lane == 0) sInv[row] = 1.0f / ssum;
        }
    }
    __syncthreads();

    // ---- phase 3: write normalized attn (full rows, zeros above diag) ----
    #pragma unroll 4
    for (int i = 0; i < 128; i++) {
        int f = tid + (i << 8); int row = f >> 10, kk = f & 1023;
        int qr = q0 + row;
        float vv = (kk <= qr) ? strip[row * STRIP + kk] * sInv[row] : 0.f;
        attn[((size_t)b << 20) + ((size_t)qr << 10) + kk] = vv;
    }

    // ---- phase 4: out = (attn @ v) ----
    const int d0 = (tid & 7) << 3;
    float oacc[8] = {};
    for (int kt = 0; kt < ntile; kt++) {
        const int k0 = kt << 6;
        __syncthreads();
        #pragma unroll
        for (int i = 0; i < 16; i++) {
            int f = tid + (i << 8); int kk = f >> 6, d = f & 63;
            sKV[kk * 68 + d] = V[((size_t)b << 16) + ((size_t)(k0 + kk) << 6) + d];
        }
        __syncthreads();
        #pragma unroll 8
        for (int kk = 0; kk < 64; kk++) {
            float p = strip[qi * STRIP + k0 + kk];
            float4 a = *(const float4*)&sKV[kk * 68 + d0];
            float4 c = *(const float4*)&sKV[kk * 68 + d0 + 4];
            oacc[0] = fmaf(p, a.x, oacc[0]); oacc[1] = fmaf(p, a.y, oacc[1]);
            oacc[2] = fmaf(p, a.z, oacc[2]); oacc[3] = fmaf(p, a.w, oacc[3]);
            oacc[4] = fmaf(p, c.x, oacc[4]); oacc[5] = fmaf(p, c.y, oacc[5]);
            oacc[6] = fmaf(p, c.z, oacc[6]); oacc[7] = fmaf(p, c.w, oacc[7]);
        }
    }
    const float inv = sInv[qi];
    const size_t ob = ((size_t)b << 16) + ((size_t)q_row << 6) + d0;
    *(float4*)&out[ob]     = make_float4(oacc[0]*inv, oacc[1]*inv, oacc[2]*inv, oacc[3]*inv);
    *(float4*)&out[ob + 4] = make_float4(oacc[4]*inv, oacc[5]*inv, oacc[6]*inv, oacc[7]*inv);
}

// ---------------------------------------------------------------------------
// Kernel 3: out[b,q,d] += sum_k attn[b,q,k] * R_v[q,k,d].  Grid: 1024 q.
// ---------------------------------------------------------------------------
__global__ void __launch_bounds__(256) k_rv(const float* __restrict__ attn,
                                            const float* __restrict__ Rv,
                                            float* __restrict__ out)
{
    const int q   = blockIdx.x;
    const int tid = threadIdx.x;
    const int ntile = (q >> 6) + 1;

    __shared__ float sAt[64 * 68];   // [kk][b]
    __shared__ float sRt[64 * 68];   // [kk][d]

    const int b0 = (tid >> 4) << 2, d0 = (tid & 15) << 2;
    float acc[4][4] = {};

    for (int kt = 0; kt < ntile; kt++) {
        const int k0 = kt << 6;
        __syncthreads();
        #pragma unroll
        for (int i = 0; i < 16; i++) {
            int f = tid + (i << 8); int bb = f >> 6, kk = f & 63;
            sAt[kk * 68 + bb] = attn[((size_t)bb << 20) + ((size_t)q << 10) + (size_t)(k0 + kk)];
        }
        #pragma unroll
        for (int i = 0; i < 16; i++) {
            int f = tid + (i << 8); int kk = f >> 6, d = f & 63;
            sRt[kk * 68 + d] = Rv[(((size_t)q << 10) + (size_t)(k0 + kk)) * 64 + d];
        }
        __syncthreads();
        #pragma unroll 8
        for (int kk = 0; kk < 64; kk++) {
            float4 a = *(const float4*)&sAt[kk * 68 + b0];
            float4 r = *(const float4*)&sRt[kk * 68 + d0];
            float aa[4] = {a.x, a.y, a.z, a.w};
            float rr[4] = {r.x, r.y, r.z, r.w};
            #pragma unroll
            for (int i = 0; i < 4; i++)
                #pragma unroll
                for (int j = 0; j < 4; j++)
                    acc[i][j] = fmaf(aa[i], rr[j], acc[i][j]);
        }
    }
    #pragma unroll
    for (int i = 0; i < 4; i++) {
        size_t ob = ((size_t)(b0 + i) << 16) + ((size_t)q << 6) + d0;
        float4 o = *(float4*)&out[ob];
        o.x += acc[i][0]; o.y += acc[i][1]; o.z += acc[i][2]; o.w += acc[i][3];
        *(float4*)&out[ob] = o;
    }
}

// ---------------------------------------------------------------------------
extern "C" void kernel_launch(void* const* d_in, const int* in_sizes, int n_in,
                              void* d_out, int out_size)
{
    const float* Q  = (const float*)d_in[0];
    const float* K  = (const float*)d_in[1];
    const float* V  = (const float*)d_in[2];
    const float* Rk = (const float*)d_in[3];
    const float* Rv = (const float*)d_in[4];
    float* out  = (float*)d_out;
    float* attn = out + SZ_OUT;

    const int smem2 = (32 * STRIP + 32 * 68 + 64 * 68) * (int)sizeof(float);
    cudaFuncSetAttribute(k_attn, cudaFuncAttributeMaxDynamicSharedMemorySize, smem2);

    k_bias<<<dim3(16, 1024), 256>>>(Q, Rk, attn);
    k_attn<<<dim3(64, 32), 256, smem2>>>(Q, K, V, attn, out);
    k_rv<<<1024, 256>>>(attn, Rv, out);
}

// round 5
// speedup vs baseline: 1.9728x; 1.9728x over previous
#include <cuda_runtime.h>

#define SZ_OUT (64ull * 1024ull * 64ull)
#define STRIP 1028   // 32 rows, padded (multiple of 4 for float4, +4 vs 1024)

// ---------------------------------------------------------------------------
// Kernel 1: bias[b,q,k] = sum_d Q[b,q,d] * R_k[q,k,d]   (written into attn
// region as scratch; only causal tiles). Grid: (16 k-tiles, 1024 q).
// ---------------------------------------------------------------------------
__global__ void __launch_bounds__(256) k_bias(const float* __restrict__ Q,
                                              const float* __restrict__ Rk,
                                              float* __restrict__ attn)
{
    const int q  = blockIdx.y;
    const int k0 = blockIdx.x << 6;
    if (k0 > q) return;

    __shared__ float sQd[64 * 68];   // [d][b]
    __shared__ float sRt[64 * 68];   // [d][kk]
    const int tid = threadIdx.x;

    #pragma unroll
    for (int i = 0; i < 16; i++) {
        int f = tid + (i << 8); int b = f >> 6, d = f & 63;
        sQd[d * 68 + b] = Q[((size_t)b << 16) + ((size_t)q << 6) + d];
    }
    #pragma unroll
    for (int i = 0; i < 16; i++) {
        int f = tid + (i << 8); int kk = f >> 6, d = f & 63;
        sRt[d * 68 + kk] = Rk[(((size_t)q << 10) + (size_t)(k0 + kk)) * 64 + d];
    }
    __syncthreads();

    const int b0 = (tid >> 4) << 2, kk0 = (tid & 15) << 2;
    float acc[4][4] = {};
    #pragma unroll 8
    for (int d = 0; d < 64; d++) {
        float4 qv = *(const float4*)&sQd[d * 68 + b0];
        float4 rv = *(const float4*)&sRt[d * 68 + kk0];
        float qa[4] = {qv.x, qv.y, qv.z, qv.w};
        float ra[4] = {rv.x, rv.y, rv.z, rv.w};
        #pragma unroll
        for (int i = 0; i < 4; i++)
            #pragma unroll
            for (int j = 0; j < 4; j++)
                acc[i][j] = fmaf(qa[i], ra[j], acc[i][j]);
    }
    #pragma unroll
    for (int i = 0; i < 4; i++) {
        size_t base = ((size_t)(b0 + i) << 20) + ((size_t)q << 10) + (size_t)(k0 + kk0);
        *(float4*)&attn[base] = make_float4(acc[i][0], acc[i][1], acc[i][2], acc[i][3]);
    }
}

// ---------------------------------------------------------------------------
// Kernel 2: per (b, 32-row q strip). 512 threads, ~205 KB smem.
//  phase1: scores = (q@k^T + bias)*0.125, causal, into smem strip (256-wide
//          k tiles, 4q x 4k per thread)
//  phase2: row softmax (exp into strip, 1/sum into sInv)
//  phase3: write normalized attn to gmem (zeros above diagonal)
//  phase4: out = attn @ v (split-K across 2 thread groups + smem reduce)
// ---------------------------------------------------------------------------
__global__ void __launch_bounds__(512) k_attn(const float* __restrict__ Q,
                                              const float* __restrict__ K,
                                              const float* __restrict__ V,
                                              float* attn,
                                              float* __restrict__ out)
{
    extern __shared__ float sm[];
    float* strip = sm;                          // [32][1028]
    float* sQd   = strip + 32 * STRIP;          // [d][qi] stride 36 (also phase4 reduce buf)
    float* sKV   = sQd + 64 * 36;               // phase1: [d][kk] stride 260 (16640 f);
                                                // phase4: [kk][d] stride 68, 256 rows (17408 f)
    __shared__ float sInv[32];

    const int b   = blockIdx.x;
    const int q0  = blockIdx.y << 5;
    const int tid = threadIdx.x;
    const int ntile = (q0 + 32 + 255) >> 8;     // 256-wide k tiles

    // load Q strip: sQd[d*36 + qi]
    #pragma unroll
    for (int i = 0; i < 4; i++) {
        int f = tid + (i << 9); int qi = f >> 6, d = f & 63;
        sQd[d * 36 + qi] = Q[((size_t)b << 16) + ((size_t)(q0 + qi) << 6) + d];
    }

    // ---- phase 1: scores ----
    const int qi0 = (tid >> 6) << 2;      // 4 q rows
    const int kx0 = (tid & 63) << 2;      // 4 k cols within 256-tile

    for (int kt = 0; kt < ntile; kt++) {
        const int k0 = kt << 8;
        __syncthreads();
        #pragma unroll
        for (int i = 0; i < 32; i++) {
            int f = tid + (i << 9); int kk = f >> 6, d = f & 63;
            sKV[d * 260 + kk] = K[((size_t)b << 16) + ((size_t)(k0 + kk) << 6) + d];
        }
        __syncthreads();

        float acc[4][4] = {};
        #pragma unroll 8
        for (int d = 0; d < 64; d++) {
            float4 qv = *(const float4*)&sQd[d * 36 + qi0];
            float4 kv = *(const float4*)&sKV[d * 260 + kx0];
            float qa[4] = {qv.x, qv.y, qv.z, qv.w};
            float ka[4] = {kv.x, kv.y, kv.z, kv.w};
            #pragma unroll
            for (int i = 0; i < 4; i++)
                #pragma unroll
                for (int j = 0; j < 4; j++)
                    acc[i][j] = fmaf(qa[i], ka[j], acc[i][j]);
        }
        #pragma unroll
        for (int i = 0; i < 4; i++) {
            const int q_row = q0 + qi0 + i;
            const int kg = k0 + kx0;
            float4 bs = *(const float4*)&attn[((size_t)b << 20) + ((size_t)q_row << 10) + kg];
            float s0 = (kg     <= q_row) ? (acc[i][0] + bs.x) * 0.125f : 0.f;
            float s1 = (kg + 1 <= q_row) ? (acc[i][1] + bs.y) * 0.125f : 0.f;
            float s2 = (kg + 2 <= q_row) ? (acc[i][2] + bs.z) * 0.125f : 0.f;
            float s3 = (kg + 3 <= q_row) ? (acc[i][3] + bs.w) * 0.125f : 0.f;
            *(float4*)&strip[(qi0 + i) * STRIP + kg] = make_float4(s0, s1, s2, s3);
        }
    }
    __syncthreads();

    // ---- phase 2: softmax per row (16 warps, 2 rows each) ----
    {
        const int lane = tid & 31, w = tid >> 5;
        #pragma unroll
        for (int r = 0; r < 2; r++) {
            int row = (w << 1) + r;
            int qr  = q0 + row;
            float m = -1e30f;
            for (int kk = lane; kk <= qr; kk += 32)
                m = fmaxf(m, strip[row * STRIP + kk]);
            #pragma unroll
            for (int o = 16; o; o >>= 1)
                m = fmaxf(m, __shfl_xor_sync(0xffffffffu, m, o));
            float ssum = 0.f;
            for (int kk = lane; kk <= qr; kk += 32) {
                float e = __expf(strip[row * STRIP + kk] - m);
                strip[row * STRIP + kk] = e;
                ssum += e;
            }
            #pragma unroll
            for (int o = 16; o; o >>= 1)
                ssum += __shfl_xor_sync(0xffffffffu, ssum, o);
            if (lane == 0) sInv[row] = 1.0f / ssum;
        }
    }
    __syncthreads();

    // ---- phase 3: write normalized attn (float4, zeros above diagonal) ----
    #pragma unroll
    for (int i = 0; i < 16; i++) {
        int f = tid + (i << 9);           // 8192 float4 slots
        int row = f >> 8;
        int kc  = (f & 255) << 2;
        int qr  = q0 + row;
        float inv = sInv[row];
        float4 e = *(const float4*)&strip[row * STRIP + kc];
        float4 o;
        o.x = (kc     <= qr) ? e.x * inv : 0.f;
        o.y = (kc + 1 <= qr) ? e.y * inv : 0.f;
        o.z = (kc + 2 <= qr) ? e.z * inv : 0.f;
        o.w = (kc + 3 <= qr) ? e.w * inv : 0.f;
        *(float4*)&attn[((size_t)b << 20) + ((size_t)qr << 10) + kc] = o;
    }

    // ---- phase 4: out = attn @ v, split-K over 2 groups of 256 threads ----
    const int g    = tid >> 8;
    const int tid2 = tid & 255;
    const int r0   = (tid2 >> 4) << 1;    // 2 q rows
    const int d0   = (tid2 & 15) << 2;    // 4 d cols
    float oacc[2][4] = {};

    for (int kt = 0; kt < ntile; kt++) {
        const int k0 = kt << 8;
        __syncthreads();
        #pragma unroll
        for (int i = 0; i < 32; i++) {
            int f = tid + (i << 9); int kk = f >> 6, d = f & 63;
            sKV[kk * 68 + d] = V[((size_t)b << 16) + ((size_t)(k0 + kk) << 6) + d];
        }
        __syncthreads();
        const int kbeg = g << 7;
        #pragma unroll 8
        for (int kk = kbeg; kk < kbeg + 128; kk++) {
            float p0 = strip[r0 * STRIP + k0 + kk];
            float p1 = strip[(r0 + 1) * STRIP + k0 + kk];
            float4 v = *(const float4*)&sKV[kk * 68 + d0];
            oacc[0][0] = fmaf(p0, v.x, oacc[0][0]); oacc[0][1] = fmaf(p0, v.y, oacc[0][1]);
            oacc[0][2] = fmaf(p0, v.z, oacc[0][2]); oacc[0][3] = fmaf(p0, v.w, oacc[0][3]);
            oacc[1][0] = fmaf(p1, v.x, oacc[1][0]); oacc[1][1] = fmaf(p1, v.y, oacc[1][1]);
            oacc[1][2] = fmaf(p1, v.z, oacc[1][2]); oacc[1][3] = fmaf(p1, v.w, oacc[1][3]);
        }
    }
    __syncthreads();
    // group 1 deposits partials into sQd (2048 floats), group 0 reduces + writes
    if (g == 1) {
        #pragma unroll
        for (int i = 0; i < 2; i++)
            *(float4*)&sQd[(r0 + i) * 64 + d0] =
                make_float4(oacc[i][0], oacc[i][1], oacc[i][2], oacc[i][3]);
    }
    __syncthreads();
    if (g == 0) {
        #pragma unroll
        for (int i = 0; i < 2; i++) {
            float4 p = *(const float4*)&sQd[(r0 + i) * 64 + d0];
            float inv = sInv[r0 + i];
            float4 o;
            o.x = (oacc[i][0] + p.x) * inv;
            o.y = (oacc[i][1] + p.y) * inv;
            o.z = (oacc[i][2] + p.z) * inv;
            o.w = (oacc[i][3] + p.w) * inv;
            *(float4*)&out[((size_t)b << 16) + ((size_t)(q0 + r0 + i) << 6) + d0] = o;
        }
    }
}

// ---------------------------------------------------------------------------
// Kernel 3: out[b,q,d] += sum_k attn[b,q,k] * R_v[q,k,d].  Grid: 1024 q.
// ---------------------------------------------------------------------------
__global__ void __launch_bounds__(256) k_rv(const float* __restrict__ attn,
                                            const float* __restrict__ Rv,
                                            float* __restrict__ out)
{
    const int q   = blockIdx.x;
    const int tid = threadIdx.x;
    const int ntile = (q >> 6) + 1;

    __shared__ float sAt[64 * 68];   // [kk][b]
    __shared__ float sRt[64 * 68];   // [kk][d]

    const int b0 = (tid >> 4) << 2, d0 = (tid & 15) << 2;
    float acc[4][4] = {};

    for (int kt = 0; kt < ntile; kt++) {
        const int k0 = kt << 6;
        __syncthreads();
        #pragma unroll
        for (int i = 0; i < 16; i++) {
            int f = tid + (i << 8); int bb = f >> 6, kk = f & 63;
            sAt[kk * 68 + bb] = attn[((size_t)bb << 20) + ((size_t)q << 10) + (size_t)(k0 + kk)];
        }
        #pragma unroll
        for (int i = 0; i < 16; i++) {
            int f = tid + (i << 8); int kk = f >> 6, d = f & 63;
            sRt[kk * 68 + d] = Rv[(((size_t)q << 10) + (size_t)(k0 + kk)) * 64 + d];
        }
        __syncthreads();
        #pragma unroll 8
        for (int kk = 0; kk < 64; kk++) {
            float4 a = *(const float4*)&sAt[kk * 68 + b0];
            float4 r = *(const float4*)&sRt[kk * 68 + d0];
            float aa[4] = {a.x, a.y, a.z, a.w};
            float rr[4] = {r.x, r.y, r.z, r.w};
            #pragma unroll
            for (int i = 0; i < 4; i++)
                #pragma unroll
                for (int j = 0; j < 4; j++)
                    acc[i][j] = fmaf(aa[i], rr[j], acc[i][j]);
        }
    }
    #pragma unroll
    for (int i = 0; i < 4; i++) {
        size_t ob = ((size_t)(b0 + i) << 16) + ((size_t)q << 6) + d0;
        float4 o = *(float4*)&out[ob];
        o.x += acc[i][0]; o.y += acc[i][1]; o.z += acc[i][2]; o.w += acc[i][3];
        *(float4*)&out[ob] = o;
    }
}

// ---------------------------------------------------------------------------
extern "C" void kernel_launch(void* const* d_in, const int* in_sizes, int n_in,
                              void* d_out, int out_size)
{
    const float* Q  = (const float*)d_in[0];
    const float* K  = (const float*)d_in[1];
    const float* V  = (const float*)d_in[2];
    const float* Rk = (const float*)d_in[3];
    const float* Rv = (const float*)d_in[4];
    float* out  = (float*)d_out;
    float* attn = out + SZ_OUT;

    // sKV must hold max(phase1: 64*260, phase4: 256*68) = 17408 floats
    const int smem2 = (32 * STRIP + 64 * 36 + 256 * 68) * (int)sizeof(float);
    cudaFuncSetAttribute(k_attn, cudaFuncAttributeMaxDynamicSharedMemorySize, smem2);

    k_bias<<<dim3(16, 1024), 256>>>(Q, Rk, attn);
    k_attn<<<dim3(64, 32), 512, smem2>>>(Q, K, V, attn, out);
    k_rv<<<1024, 256>>>(attn, Rv, out);
}